// round 1
// baseline (speedup 1.0000x reference)
#include <cuda_runtime.h>
#include <math.h>

// Problem sizes (fixed by the reference)
#define Nz 16384
#define Dd 256
#define Kk 1024

#define BM 32      // rows per block
#define BN 128     // centroid-column tile
#define BK 32      // k chunk
#define AS 36      // A_s k-stride (words), padded
#define BS 132     // B_s k-stride (words), padded (16B-aligned rows: 132*4=528)
#define LS 1024    // logits row stride (words)
#define BBUF 4224  // BK*BS = one B buffer in words

// Shared memory layout (floats):
//   [0,     32768)  logits   BM x 1024
//   [32768, 41984)  A_s      256 x AS   (z tile transposed: [k][row])
//   [41984, 50432)  B_s      2 x BK x BS (centroid chunk transposed: [k][col])
//   [50432, 50688)  zsqp     32 x 8 partial row norms
//   [50688, 50720)  zsq      32 row norms
#define SM_FLOATS 50720
#define SM_BYTES  (SM_FLOATS * 4)

// Scratch (device globals: no allocation allowed)
__device__ __align__(16) float g_c_sq[Kk];
__device__ __align__(16) float g_counts[Kk];
__device__ __align__(16) float g_dw[Kk * Dd];
__device__ __align__(16) float g_ncs[Kk];

// ---------------------------------------------------------------------------
// Prep: c_sq[k] = ||centroid_k||^2 ; zero counts and dw (every launch: graph replays)
// ---------------------------------------------------------------------------
__global__ void prep_kernel(const float* __restrict__ cent) {
    int k = blockIdx.x;          // 0..1023
    int t = threadIdx.x;         // 0..255 (= D)
    float v = cent[k * Dd + t];
    float s = v * v;
    #pragma unroll
    for (int o = 16; o > 0; o >>= 1) s += __shfl_down_sync(0xffffffffu, s, o);
    __shared__ float red[8];
    if ((t & 31) == 0) red[t >> 5] = s;
    __syncthreads();
    if (t == 0) {
        float x = 0.f;
        #pragma unroll
        for (int i = 0; i < 8; i++) x += red[i];
        g_c_sq[k]   = x;
        g_counts[k] = 0.f;
    }
    g_dw[k * Dd + t] = 0.f;
}

// ---------------------------------------------------------------------------
// Main fused kernel: distances -> softmax(gamma) -> argmin -> recons + EMA scatters
// Block: 256 threads = 8 warps. warp w == thread-row tr; lane == thread-col tc.
// Thread tile: rows 4*tr..4*tr+3, cols (per BN tile) 4*tc..4*tc+3.
// ---------------------------------------------------------------------------
__device__ __forceinline__ void ldg_chunk(float4 pf[4], const float* __restrict__ cent,
                                          int col0, int kc, int bc, int bseg) {
    #pragma unroll
    for (int p = 0; p < 4; p++) {
        int c = bc + 32 * p;
        pf[p] = *reinterpret_cast<const float4*>(
            cent + (size_t)(col0 + c) * Dd + kc * BK + bseg * 4);
    }
}

__device__ __forceinline__ void sts_chunk(const float4 pf[4], float* Bbuf,
                                          int bc, int bseg) {
    #pragma unroll
    for (int p = 0; p < 4; p++) {
        int c  = bc + 32 * p;
        int kb = bseg * 4;
        Bbuf[(kb + 0) * BS + c] = pf[p].x;
        Bbuf[(kb + 1) * BS + c] = pf[p].y;
        Bbuf[(kb + 2) * BS + c] = pf[p].z;
        Bbuf[(kb + 3) * BS + c] = pf[p].w;
    }
}

__global__ void __launch_bounds__(256, 1)
main_kernel(const float* __restrict__ z, const float* __restrict__ cent,
            float* __restrict__ recons, float* __restrict__ gamma)
{
    extern __shared__ float sm[];
    float* logits = sm;
    float* A_s    = sm + 32768;
    float* B_s    = sm + 41984;
    float* zsqp   = sm + 50432;
    float* zsq    = sm + 50688;

    const int tid  = threadIdx.x;
    const int lane = tid & 31;
    const int w    = tid >> 5;    // warp id == tr
    const int tr   = w;
    const int tc   = lane;
    const int row0 = blockIdx.x * BM;

    // ---- stage z tile (transposed) + row norms (deterministic partials) ----
    {
        int r   = tid >> 3;       // 0..31
        int seg = tid & 7;        // 0..7
        const float4* zr = reinterpret_cast<const float4*>(z + (size_t)(row0 + r) * Dd);
        float lsum = 0.f;
        #pragma unroll
        for (int j = 0; j < 8; j++) {
            int   k4 = seg + 8 * j;     // float4 index 0..63
            float4 v = zr[k4];
            int   kb = k4 * 4;
            A_s[(kb + 0) * AS + r] = v.x;
            A_s[(kb + 1) * AS + r] = v.y;
            A_s[(kb + 2) * AS + r] = v.z;
            A_s[(kb + 3) * AS + r] = v.w;
            lsum += v.x * v.x + v.y * v.y + v.z * v.z + v.w * v.w;
        }
        zsqp[r * 8 + seg] = lsum;
    }
    __syncthreads();
    if (tid < 32) {
        float s = 0.f;
        #pragma unroll
        for (int i = 0; i < 8; i++) s += zsqp[tid * 8 + i];
        zsq[tid] = s;
    }
    __syncthreads();

    const int bc   = tid >> 3;    // staging: col within pass
    const int bseg = tid & 7;     // staging: k segment

    // ---- GEMM over 8 column tiles of 128 centroids ----
    float4 pf[4];
    #pragma unroll 1
    for (int ct = 0; ct < 8; ct++) {
        const int col0 = ct * BN;

        ldg_chunk(pf, cent, col0, 0, bc, bseg);
        sts_chunk(pf, B_s, bc, bseg);              // buffer 0 = chunk 0
        ldg_chunk(pf, cent, col0, 1, bc, bseg);    // chunk 1 in flight
        __syncthreads();

        float acc[4][4];
        #pragma unroll
        for (int i = 0; i < 4; i++)
            #pragma unroll
            for (int j = 0; j < 4; j++) acc[i][j] = 0.f;

        #pragma unroll 1
        for (int kc = 0; kc < 8; kc++) {
            // All warps passed the barrier ending kc-1, so buffer (kc+1)&1
            // (read during compute kc-1) is free to overwrite.
            if (kc < 7) sts_chunk(pf, B_s + ((kc + 1) & 1) * BBUF, bc, bseg);
            if (kc < 6) ldg_chunk(pf, cent, col0, kc + 2, bc, bseg);

            const float* Ab = A_s + (kc * BK) * AS + 4 * tr;
            const float* Bb = B_s + (kc & 1) * BBUF + 4 * tc;
            #pragma unroll
            for (int kk = 0; kk < BK; kk++) {
                float4 a = *reinterpret_cast<const float4*>(Ab + kk * AS);
                float4 b = *reinterpret_cast<const float4*>(Bb + kk * BS);
                acc[0][0] = fmaf(a.x, b.x, acc[0][0]);
                acc[0][1] = fmaf(a.x, b.y, acc[0][1]);
                acc[0][2] = fmaf(a.x, b.z, acc[0][2]);
                acc[0][3] = fmaf(a.x, b.w, acc[0][3]);
                acc[1][0] = fmaf(a.y, b.x, acc[1][0]);
                acc[1][1] = fmaf(a.y, b.y, acc[1][1]);
                acc[1][2] = fmaf(a.y, b.z, acc[1][2]);
                acc[1][3] = fmaf(a.y, b.w, acc[1][3]);
                acc[2][0] = fmaf(a.z, b.x, acc[2][0]);
                acc[2][1] = fmaf(a.z, b.y, acc[2][1]);
                acc[2][2] = fmaf(a.z, b.z, acc[2][2]);
                acc[2][3] = fmaf(a.z, b.w, acc[2][3]);
                acc[3][0] = fmaf(a.w, b.x, acc[3][0]);
                acc[3][1] = fmaf(a.w, b.y, acc[3][1]);
                acc[3][2] = fmaf(a.w, b.z, acc[3][2]);
                acc[3][3] = fmaf(a.w, b.w, acc[3][3]);
            }
            __syncthreads();
        }

        // logit = -5*dist = 10*dot - 5*zsq - 5*csq ; store to smem (own rows only)
        float4 csq4 = *reinterpret_cast<const float4*>(g_c_sq + col0 + 4 * tc);
        float cm0 = -5.f * csq4.x, cm1 = -5.f * csq4.y;
        float cm2 = -5.f * csq4.z, cm3 = -5.f * csq4.w;
        #pragma unroll
        for (int i = 0; i < 4; i++) {
            float zb = -5.f * zsq[4 * tr + i];
            float4 lg;
            lg.x = fmaf(10.f, acc[i][0], zb + cm0);
            lg.y = fmaf(10.f, acc[i][1], zb + cm1);
            lg.z = fmaf(10.f, acc[i][2], zb + cm2);
            lg.w = fmaf(10.f, acc[i][3], zb + cm3);
            *reinterpret_cast<float4*>(logits + (4 * tr + i) * LS + col0 + 4 * tc) = lg;
        }
    }

    // ---- softmax + argmax + recons + EMA scatters (each warp owns its 4 rows,
    //      which it alone produced -> no barrier needed) ----
    #pragma unroll 1
    for (int r = 0; r < 4; r++) {
        const int row  = 4 * w + r;
        const int rowG = row0 + row;
        const float* L = logits + row * LS;

        // pass 1: max + first-index argmax (ascending scan per lane, min-index tiebreak)
        float m = -1e30f; int mi = 0;
        #pragma unroll
        for (int j = 0; j < 8; j++) {
            int    b0 = (lane + 32 * j) * 4;
            float4 v  = *reinterpret_cast<const float4*>(L + b0);
            if (v.x > m) { m = v.x; mi = b0;     }
            if (v.y > m) { m = v.y; mi = b0 + 1; }
            if (v.z > m) { m = v.z; mi = b0 + 2; }
            if (v.w > m) { m = v.w; mi = b0 + 3; }
        }
        #pragma unroll
        for (int o = 16; o > 0; o >>= 1) {
            float om = __shfl_xor_sync(0xffffffffu, m,  o);
            int   oi = __shfl_xor_sync(0xffffffffu, mi, o);
            if (om > m || (om == m && oi < mi)) { m = om; mi = oi; }
        }

        // pass 2: sum of exp
        float s = 0.f;
        #pragma unroll
        for (int j = 0; j < 8; j++) {
            float4 v = *reinterpret_cast<const float4*>(L + (lane + 32 * j) * 4);
            s += __expf(v.x - m) + __expf(v.y - m) + __expf(v.z - m) + __expf(v.w - m);
        }
        #pragma unroll
        for (int o = 16; o > 0; o >>= 1) s += __shfl_xor_sync(0xffffffffu, s, o);
        float inv = 1.f / s;

        // pass 3: write gamma
        float* G = gamma + (size_t)rowG * Kk;
        #pragma unroll
        for (int j = 0; j < 8; j++) {
            int    b0 = (lane + 32 * j) * 4;
            float4 v  = *reinterpret_cast<const float4*>(L + b0);
            float4 g;
            g.x = __expf(v.x - m) * inv;
            g.y = __expf(v.y - m) * inv;
            g.z = __expf(v.z - m) * inv;
            g.w = __expf(v.w - m) * inv;
            *reinterpret_cast<float4*>(G + b0) = g;
        }

        // recons = z + (c[k*] - z)  (matches straight-through expression exactly)
        const float4* crow = reinterpret_cast<const float4*>(cent   + (size_t)mi   * Dd);
        const float4* zrow = reinterpret_cast<const float4*>(z      + (size_t)rowG * Dd);
        float4*       rrow = reinterpret_cast<float4*>      (recons + (size_t)rowG * Dd);
        float* dwr = g_dw + (size_t)mi * Dd;
        #pragma unroll
        for (int j2 = 0; j2 < 2; j2++) {
            int d4 = lane + 32 * j2;
            float4 zv = zrow[d4];
            float4 cv = crow[d4];
            float4 rv;
            rv.x = zv.x + (cv.x - zv.x);
            rv.y = zv.y + (cv.y - zv.y);
            rv.z = zv.z + (cv.z - zv.z);
            rv.w = zv.w + (cv.w - zv.w);
            rrow[d4] = rv;
            atomicAdd(dwr + d4 * 4 + 0, zv.x);
            atomicAdd(dwr + d4 * 4 + 1, zv.y);
            atomicAdd(dwr + d4 * 4 + 2, zv.z);
            atomicAdd(dwr + d4 * 4 + 3, zv.w);
        }
        if (lane == 0) atomicAdd(&g_counts[mi], 1.f);
    }
}

// ---------------------------------------------------------------------------
// EMA cluster-size normalization (single block, K threads)
// ---------------------------------------------------------------------------
__global__ void norm_kernel(const float* __restrict__ ema_cs) {
    int k    = threadIdx.x;       // 0..1023
    int lane = k & 31;
    int wrp  = k >> 5;
    float ncs = ema_cs[k] * 0.95f + 0.05f * g_counts[k];

    __shared__ float red[32];
    __shared__ float n_sh;
    float s = ncs;
    #pragma unroll
    for (int o = 16; o > 0; o >>= 1) s += __shfl_down_sync(0xffffffffu, s, o);
    if (lane == 0) red[wrp] = s;
    __syncthreads();
    if (k < 32) {
        float x = red[k];
        #pragma unroll
        for (int o = 16; o > 0; o >>= 1) x += __shfl_down_sync(0xffffffffu, x, o);
        if (k == 0) n_sh = x;
    }
    __syncthreads();
    float n = n_sh;
    g_ncs[k] = (ncs + 1e-5f) / (n + 0.01024f) * n;   // (cs+eps)/(n+K*eps)*n
}

// ---------------------------------------------------------------------------
// new_centroids = (ema_w*0.95 + 0.05*dw) / ncs
// ---------------------------------------------------------------------------
__global__ void finalize_kernel(const float* __restrict__ ema_w, float* __restrict__ out) {
    int k = blockIdx.x;
    int d = threadIdx.x;
    size_t i = (size_t)k * Dd + d;
    out[i] = (ema_w[i] * 0.95f + 0.05f * g_dw[i]) / g_ncs[k];
}

// ---------------------------------------------------------------------------
extern "C" void kernel_launch(void* const* d_in, const int* in_sizes, int n_in,
                              void* d_out, int out_size) {
    const float* z      = (const float*)d_in[0];
    const float* cent   = (const float*)d_in[1];
    const float* ema_w  = (const float*)d_in[2];
    const float* ema_cs = (const float*)d_in[3];

    float* out    = (float*)d_out;
    float* recons = out;
    float* gamma  = out + (size_t)Nz * Dd;
    float* newc   = out + (size_t)Nz * Dd + (size_t)Nz * Kk;

    cudaFuncSetAttribute(main_kernel, cudaFuncAttributeMaxDynamicSharedMemorySize, SM_BYTES);

    prep_kernel<<<Kk, 256>>>(cent);
    main_kernel<<<Nz / BM, 256, SM_BYTES>>>(z, cent, recons, gamma);
    norm_kernel<<<1, Kk>>>(ema_cs);
    finalize_kernel<<<Kk, Dd>>>(ema_w, newc);
}

// round 3
// speedup vs baseline: 1.5982x; 1.5982x over previous
#include <cuda_runtime.h>
#include <cstdint>

// Problem sizes
#define Nz 16384
#define Dd 256
#define Kk 1024

// GEMM tiling (Keff = 768 = 3 split-terms x 256)
#define BM 128
#define BN 128
#define BK 32
#define NCH 24                 // 768 / 32
#define ASTG 4608              // floats per stage tile (128 rows x 36 stride)
#define SMEM_BYTES (4 * ASTG * 4)   // A0,A1,B0,B1

// ---------------- device scratch (no allocation allowed) ----------------
__device__ __align__(16) float g_zh[Nz * Dd];
__device__ __align__(16) float g_zl[Nz * Dd];
__device__ __align__(16) float g_ch[Kk * Dd];
__device__ __align__(16) float g_cl[Kk * Dd];
__device__ __align__(16) float g_zsq[Nz];
__device__ __align__(16) float g_csq[Kk];
__device__ __align__(16) float g_dot[(size_t)Nz * Kk];   // 64 MB
__device__ __align__(16) float g_counts[Kk];
__device__ __align__(16) float g_ncs[Kk];
__device__ __align__(16) float g_dw[Kk * Dd];

// ---------------- helpers ----------------
__device__ __forceinline__ uint32_t smem_u32(const void* p) {
    uint32_t a;
    asm("{ .reg .u64 t; cvta.to.shared.u64 t, %1; cvt.u32.u64 %0, t; }" : "=r"(a) : "l"(p));
    return a;
}
__device__ __forceinline__ void cp16(uint32_t dst, const float* src) {
    asm volatile("cp.async.cg.shared.global [%0], [%1], 16;" :: "r"(dst), "l"(src));
}
__device__ __forceinline__ void mma_tf32(float* d, const uint32_t* a, const uint32_t* b) {
    asm volatile(
        "mma.sync.aligned.m16n8k8.row.col.f32.tf32.tf32.f32 "
        "{%0,%1,%2,%3}, {%4,%5,%6,%7}, {%8,%9}, {%0,%1,%2,%3};"
        : "+f"(d[0]), "+f"(d[1]), "+f"(d[2]), "+f"(d[3])
        : "r"(a[0]), "r"(a[1]), "r"(a[2]), "r"(a[3]), "r"(b[0]), "r"(b[1]));
}

// ---------------------------------------------------------------------------
// Split z into tf32 hi/lo + row norms
// ---------------------------------------------------------------------------
__global__ void split_z_kernel(const float* __restrict__ z) {
    int row = blockIdx.x, t = threadIdx.x;          // 256 threads = D
    int i = row * Dd + t;
    float v = z[i];
    uint32_t hb; asm("cvt.rna.tf32.f32 %0, %1;" : "=r"(hb) : "f"(v));
    float h = __uint_as_float(hb);
    float l = v - h;                                 // exact residual
    uint32_t lb; asm("cvt.rna.tf32.f32 %0, %1;" : "=r"(lb) : "f"(l));
    g_zh[i] = h;
    g_zl[i] = __uint_as_float(lb);

    float s = v * v;
    #pragma unroll
    for (int o = 16; o > 0; o >>= 1) s += __shfl_down_sync(0xffffffffu, s, o);
    __shared__ float red[8];
    if ((t & 31) == 0) red[t >> 5] = s;
    __syncthreads();
    if (t == 0) {
        float x = 0.f;
        #pragma unroll
        for (int j = 0; j < 8; j++) x += red[j];
        g_zsq[row] = x;
    }
}

// ---------------------------------------------------------------------------
// Split centroids + norms + zero EMA scratch (graph replays need re-zero)
// ---------------------------------------------------------------------------
__global__ void split_c_kernel(const float* __restrict__ cent) {
    int k = blockIdx.x, t = threadIdx.x;
    int i = k * Dd + t;
    float v = cent[i];
    uint32_t hb; asm("cvt.rna.tf32.f32 %0, %1;" : "=r"(hb) : "f"(v));
    float h = __uint_as_float(hb);
    float l = v - h;
    uint32_t lb; asm("cvt.rna.tf32.f32 %0, %1;" : "=r"(lb) : "f"(l));
    g_ch[i] = h;
    g_cl[i] = __uint_as_float(lb);
    g_dw[i] = 0.f;

    float s = v * v;
    #pragma unroll
    for (int o = 16; o > 0; o >>= 1) s += __shfl_down_sync(0xffffffffu, s, o);
    __shared__ float red[8];
    if ((t & 31) == 0) red[t >> 5] = s;
    __syncthreads();
    if (t == 0) {
        float x = 0.f;
        #pragma unroll
        for (int j = 0; j < 8; j++) x += red[j];
        g_csq[k]   = x;
        g_counts[k] = 0.f;
    }
}

// ---------------------------------------------------------------------------
// Stage one K-chunk (A 128x32 + B 128x32) via cp.async
// Keff segment: s=0: zh.ch ; s=1: zl.ch ; s=2: zh.cl
// ---------------------------------------------------------------------------
__device__ __forceinline__ void stage_chunk(uint32_t su, int s, int kc,
                                            int row0, int col0, int tid) {
    const int seg  = kc >> 3;
    const int koff = (kc & 7) * BK;
    const float* Asrc = (seg == 1) ? g_zl : g_zh;
    const float* Bsrc = (seg == 2) ? g_cl : g_ch;
    const uint32_t abase = su + (uint32_t)(s * ASTG) * 4u;
    const uint32_t bbase = su + (uint32_t)((2 + s) * ASTG) * 4u;
    #pragma unroll
    for (int i = 0; i < 4; i++) {
        int idx = i * 256 + tid;
        int r = idx >> 3, f = idx & 7;          // row 0..127, float4 group 0..7
        uint32_t d = (uint32_t)(r * 36 + f * 4) * 4u;
        cp16(abase + d, Asrc + (size_t)(row0 + r) * Dd + koff + f * 4);
        cp16(bbase + d, Bsrc + (size_t)(col0 + r) * Dd + koff + f * 4);
    }
    asm volatile("cp.async.commit_group;" ::: "memory");
}

// ---------------------------------------------------------------------------
// tf32 mma.sync GEMM: dot = z @ C^T (3-term split), 1024 CTAs, 256 threads
// ---------------------------------------------------------------------------
__global__ void __launch_bounds__(256, 2) gemm_kernel() {
    extern __shared__ float sm[];
    const int tid  = threadIdx.x;
    const int w    = tid >> 5;
    const int lane = tid & 31;
    const int g    = lane >> 2;     // groupID
    const int tg   = lane & 3;      // threadID-in-group
    const int wm   = w >> 1;        // 0..3 (M)
    const int wn   = w & 1;         // 0..1 (N)
    const int mt   = blockIdx.x >> 3, nt = blockIdx.x & 7;   // nt inner: A tiles L2-reuse
    const int row0 = mt * BM, col0 = nt * BN;
    const int mbase = wm * 32, nbase = wn * 64;

    const uint32_t su = smem_u32(sm);

    float acc[2][8][4];
    #pragma unroll
    for (int i = 0; i < 2; i++)
        #pragma unroll
        for (int j = 0; j < 8; j++)
            #pragma unroll
            for (int q = 0; q < 4; q++) acc[i][j][q] = 0.f;

    stage_chunk(su, 0, 0, row0, col0, tid);
    stage_chunk(su, 1, 1, row0, col0, tid);

    #pragma unroll 1
    for (int kc = 0; kc < NCH; kc++) {
        const int s = kc & 1;
        if (kc < NCH - 1) asm volatile("cp.async.wait_group 1;" ::: "memory");
        else              asm volatile("cp.async.wait_group 0;" ::: "memory");
        __syncthreads();

        const float* As = sm + s * ASTG;
        const float* Bs = sm + (2 + s) * ASTG;

        #pragma unroll
        for (int kq = 0; kq < 4; kq++) {
            const int k0 = kq * 8;
            uint32_t a[2][4], b[8][2];
            #pragma unroll
            for (int i = 0; i < 2; i++) {
                const float* p = As + (mbase + i * 16 + g) * 36 + k0 + tg;
                a[i][0] = __float_as_uint(p[0]);
                a[i][1] = __float_as_uint(p[8 * 36]);
                a[i][2] = __float_as_uint(p[4]);
                a[i][3] = __float_as_uint(p[8 * 36 + 4]);
            }
            #pragma unroll
            for (int j = 0; j < 8; j++) {
                const float* q = Bs + (nbase + j * 8 + g) * 36 + k0 + tg;
                b[j][0] = __float_as_uint(q[0]);
                b[j][1] = __float_as_uint(q[4]);
            }
            #pragma unroll
            for (int i = 0; i < 2; i++)
                #pragma unroll
                for (int j = 0; j < 8; j++) mma_tf32(acc[i][j], a[i], b[j]);
        }
        __syncthreads();
        if (kc + 2 < NCH) stage_chunk(su, s, kc + 2, row0, col0, tid);
    }

    // Epilogue: store accumulators to g_dot
    #pragma unroll
    for (int i = 0; i < 2; i++) {
        const size_t r0 = (size_t)(row0 + mbase + i * 16 + g);
        #pragma unroll
        for (int j = 0; j < 8; j++) {
            const int col = col0 + nbase + j * 8 + 2 * tg;
            *reinterpret_cast<float2*>(g_dot + r0 * Kk + col) =
                make_float2(acc[i][j][0], acc[i][j][1]);
            *reinterpret_cast<float2*>(g_dot + (r0 + 8) * Kk + col) =
                make_float2(acc[i][j][2], acc[i][j][3]);
        }
    }
}

// ---------------------------------------------------------------------------
// Phase 2: logits -> softmax/argmax -> gamma, recons, EMA scatters
// One warp per z-row; 8 rows per block
// ---------------------------------------------------------------------------
__global__ void __launch_bounds__(256) softmax_kernel(const float* __restrict__ z,
                                                      const float* __restrict__ cent,
                                                      float* __restrict__ recons,
                                                      float* __restrict__ gamma) {
    const int w = threadIdx.x >> 5, lane = threadIdx.x & 31;
    const int row = blockIdx.x * 8 + w;
    const float* L = g_dot + (size_t)row * Kk;
    const float zb = -5.f * g_zsq[row];

    // pass 1: max + first-index argmax (ascending per-lane scan, min-index tiebreak)
    float m = -1e30f; int mi = 0;
    #pragma unroll
    for (int j = 0; j < 8; j++) {
        int b0 = (lane + 32 * j) * 4;
        float4 d = *reinterpret_cast<const float4*>(L + b0);
        float4 c = *reinterpret_cast<const float4*>(g_csq + b0);
        float l0 = fmaf(10.f, d.x, fmaf(-5.f, c.x, zb));
        float l1 = fmaf(10.f, d.y, fmaf(-5.f, c.y, zb));
        float l2 = fmaf(10.f, d.z, fmaf(-5.f, c.z, zb));
        float l3 = fmaf(10.f, d.w, fmaf(-5.f, c.w, zb));
        if (l0 > m) { m = l0; mi = b0;     }
        if (l1 > m) { m = l1; mi = b0 + 1; }
        if (l2 > m) { m = l2; mi = b0 + 2; }
        if (l3 > m) { m = l3; mi = b0 + 3; }
    }
    #pragma unroll
    for (int o = 16; o > 0; o >>= 1) {
        float om = __shfl_xor_sync(0xffffffffu, m,  o);
        int   oi = __shfl_xor_sync(0xffffffffu, mi, o);
        if (om > m || (om == m && oi < mi)) { m = om; mi = oi; }
    }

    // pass 2: sum of exp (identical logit recompute; L1/L2-resident)
    float s = 0.f;
    #pragma unroll
    for (int j = 0; j < 8; j++) {
        int b0 = (lane + 32 * j) * 4;
        float4 d = *reinterpret_cast<const float4*>(L + b0);
        float4 c = *reinterpret_cast<const float4*>(g_csq + b0);
        s += __expf(fmaf(10.f, d.x, fmaf(-5.f, c.x, zb)) - m)
           + __expf(fmaf(10.f, d.y, fmaf(-5.f, c.y, zb)) - m)
           + __expf(fmaf(10.f, d.z, fmaf(-5.f, c.z, zb)) - m)
           + __expf(fmaf(10.f, d.w, fmaf(-5.f, c.w, zb)) - m);
    }
    #pragma unroll
    for (int o = 16; o > 0; o >>= 1) s += __shfl_xor_sync(0xffffffffu, s, o);
    const float inv = 1.f / s;

    // pass 3: gamma
    float* G = gamma + (size_t)row * Kk;
    #pragma unroll
    for (int j = 0; j < 8; j++) {
        int b0 = (lane + 32 * j) * 4;
        float4 d = *reinterpret_cast<const float4*>(L + b0);
        float4 c = *reinterpret_cast<const float4*>(g_csq + b0);
        float4 gv;
        gv.x = __expf(fmaf(10.f, d.x, fmaf(-5.f, c.x, zb)) - m) * inv;
        gv.y = __expf(fmaf(10.f, d.y, fmaf(-5.f, c.y, zb)) - m) * inv;
        gv.z = __expf(fmaf(10.f, d.z, fmaf(-5.f, c.z, zb)) - m) * inv;
        gv.w = __expf(fmaf(10.f, d.w, fmaf(-5.f, c.w, zb)) - m) * inv;
        *reinterpret_cast<float4*>(G + b0) = gv;
    }

    // recons = z + (c[k*] - z); EMA scatters
    const float4* crow = reinterpret_cast<const float4*>(cent   + (size_t)mi  * Dd);
    const float4* zrow = reinterpret_cast<const float4*>(z      + (size_t)row * Dd);
    float4*       rrow = reinterpret_cast<float4*>      (recons + (size_t)row * Dd);
    float* dwr = g_dw + (size_t)mi * Dd;
    #pragma unroll
    for (int j2 = 0; j2 < 2; j2++) {
        int d4 = lane + 32 * j2;
        float4 zv = zrow[d4];
        float4 cv = crow[d4];
        float4 rv;
        rv.x = zv.x + (cv.x - zv.x);
        rv.y = zv.y + (cv.y - zv.y);
        rv.z = zv.z + (cv.z - zv.z);
        rv.w = zv.w + (cv.w - zv.w);
        rrow[d4] = rv;
        atomicAdd(dwr + d4 * 4 + 0, zv.x);
        atomicAdd(dwr + d4 * 4 + 1, zv.y);
        atomicAdd(dwr + d4 * 4 + 2, zv.z);
        atomicAdd(dwr + d4 * 4 + 3, zv.w);
    }
    if (lane == 0) atomicAdd(&g_counts[mi], 1.f);
}

// ---------------------------------------------------------------------------
__global__ void norm_kernel(const float* __restrict__ ema_cs) {
    int k = threadIdx.x, lane = k & 31, wrp = k >> 5;
    float ncs = ema_cs[k] * 0.95f + 0.05f * g_counts[k];
    __shared__ float red[32];
    __shared__ float n_sh;
    float s = ncs;
    #pragma unroll
    for (int o = 16; o > 0; o >>= 1) s += __shfl_down_sync(0xffffffffu, s, o);
    if (lane == 0) red[wrp] = s;
    __syncthreads();
    if (k < 32) {
        float x = red[k];
        #pragma unroll
        for (int o = 16; o > 0; o >>= 1) x += __shfl_down_sync(0xffffffffu, x, o);
        if (k == 0) n_sh = x;
    }
    __syncthreads();
    float n = n_sh;
    g_ncs[k] = (ncs + 1e-5f) / (n + 0.01024f) * n;
}

__global__ void finalize_kernel(const float* __restrict__ ema_w, float* __restrict__ out) {
    int k = blockIdx.x, d = threadIdx.x;
    size_t i = (size_t)k * Dd + d;
    out[i] = (ema_w[i] * 0.95f + 0.05f * g_dw[i]) / g_ncs[k];
}

// ---------------------------------------------------------------------------
extern "C" void kernel_launch(void* const* d_in, const int* in_sizes, int n_in,
                              void* d_out, int out_size) {
    const float* z      = (const float*)d_in[0];
    const float* cent   = (const float*)d_in[1];
    const float* ema_w  = (const float*)d_in[2];
    const float* ema_cs = (const float*)d_in[3];

    float* out    = (float*)d_out;
    float* recons = out;
    float* gamma  = out + (size_t)Nz * Dd;
    float* newc   = out + (size_t)Nz * Dd + (size_t)Nz * Kk;

    cudaFuncSetAttribute(gemm_kernel, cudaFuncAttributeMaxDynamicSharedMemorySize, SMEM_BYTES);

    split_z_kernel<<<Nz, 256>>>(z);
    split_c_kernel<<<Kk, 256>>>(cent);
    gemm_kernel<<<(Nz / BM) * (Kk / BN), 256, SMEM_BYTES>>>();
    softmax_kernel<<<Nz / 8, 256>>>(z, cent, recons, gamma);
    norm_kernel<<<1, Kk>>>(ema_cs);
    finalize_kernel<<<Kk, Dd>>>(ema_w, newc);
}

// round 4
// speedup vs baseline: 2.6375x; 1.6503x over previous
#include <cuda_runtime.h>
#include <cuda_fp16.h>
#include <cstdint>

// Problem sizes
#define Nz 16384
#define Dd 256
#define Kk 1024

// GEMM tiling
#define BM 128
#define BN 128
#define BK 32                    // k floats per chunk
#define NCH (Dd / BK)            // 8 chunks
#define TSTR 40                  // tile row stride in halves (conflict-free)
#define T_H  (128 * TSTR)        // tile size in halves (5120)
#define STG_H (4 * T_H)          // stage: Azh, Azl, Bch, Bcl
#define SMEM_BYTES (2 * STG_H * 2)   // 2 stages * halves*2B = 81920

// ---------------- device scratch ----------------
__device__ __align__(16) __half g_zh[Nz * Dd];
__device__ __align__(16) __half g_zl[Nz * Dd];
__device__ __align__(16) __half g_ch[Kk * Dd];
__device__ __align__(16) __half g_cl[Kk * Dd];
__device__ __align__(16) float  g_csq[Kk];
__device__ __align__(16) float  g_dot[(size_t)Nz * Kk];   // stores LOGITS (10*dot-5*csq)
__device__ __align__(16) float  g_counts[Kk];
__device__ __align__(16) float  g_ncs[Kk];
__device__ __align__(16) float  g_dw[Kk * Dd];

// ---------------- helpers ----------------
__device__ __forceinline__ uint32_t smem_u32(const void* p) {
    uint32_t a;
    asm("{ .reg .u64 t; cvta.to.shared.u64 t, %1; cvt.u32.u64 %0, t; }" : "=r"(a) : "l"(p));
    return a;
}
__device__ __forceinline__ void cp16(uint32_t dst, const void* src) {
    asm volatile("cp.async.cg.shared.global [%0], [%1], 16;" :: "r"(dst), "l"(src));
}
__device__ __forceinline__ void mma_f16(float* d, const uint32_t* a, const uint32_t* b) {
    asm volatile(
        "mma.sync.aligned.m16n8k16.row.col.f32.f16.f16.f32 "
        "{%0,%1,%2,%3}, {%4,%5,%6,%7}, {%8,%9}, {%0,%1,%2,%3};"
        : "+f"(d[0]), "+f"(d[1]), "+f"(d[2]), "+f"(d[3])
        : "r"(a[0]), "r"(a[1]), "r"(a[2]), "r"(a[3]), "r"(b[0]), "r"(b[1]));
}

// ---------------------------------------------------------------------------
// Split z into fp16 hi/lo (vectorized; no row norms needed: softmax is
// shift-invariant so the -5*zsq row constant is dropped everywhere)
// ---------------------------------------------------------------------------
__global__ void split_z_kernel(const float* __restrict__ z) {
    int idx = blockIdx.x * 256 + threadIdx.x;          // over Nz*Dd/4
    float4 v = reinterpret_cast<const float4*>(z)[idx];
    __half hx = __float2half(v.x), hy = __float2half(v.y);
    __half hz = __float2half(v.z), hw = __float2half(v.w);
    __half lx = __float2half(v.x - __half2float(hx));
    __half ly = __float2half(v.y - __half2float(hy));
    __half lz = __float2half(v.z - __half2float(hz));
    __half lw = __float2half(v.w - __half2float(hw));
    half2 h01 = __halves2half2(hx, hy), h23 = __halves2half2(hz, hw);
    half2 l01 = __halves2half2(lx, ly), l23 = __halves2half2(lz, lw);
    reinterpret_cast<half2*>(g_zh)[idx * 2]     = h01;
    reinterpret_cast<half2*>(g_zh)[idx * 2 + 1] = h23;
    reinterpret_cast<half2*>(g_zl)[idx * 2]     = l01;
    reinterpret_cast<half2*>(g_zl)[idx * 2 + 1] = l23;
}

// ---------------------------------------------------------------------------
// Split centroids + csq + zero EMA scratch (graph replays need re-zero)
// ---------------------------------------------------------------------------
__global__ void split_c_kernel(const float* __restrict__ cent) {
    int k = blockIdx.x, t = threadIdx.x;
    int i = k * Dd + t;
    float v = cent[i];
    __half h = __float2half(v);
    __half l = __float2half(v - __half2float(h));
    g_ch[i] = h;
    g_cl[i] = l;
    g_dw[i] = 0.f;

    float s = v * v;
    #pragma unroll
    for (int o = 16; o > 0; o >>= 1) s += __shfl_down_sync(0xffffffffu, s, o);
    __shared__ float red[8];
    if ((t & 31) == 0) red[t >> 5] = s;
    __syncthreads();
    if (t == 0) {
        float x = 0.f;
        #pragma unroll
        for (int j = 0; j < 8; j++) x += red[j];
        g_csq[k]    = x;
        g_counts[k] = 0.f;
    }
}

// ---------------------------------------------------------------------------
// Stage one K-chunk: Azh, Azl (128x32h) + Bch, Bcl (128x32h) via cp.async
// ---------------------------------------------------------------------------
__device__ __forceinline__ void stage_chunk(uint32_t su, int s, int kc,
                                            int row0, int col0, int tid) {
    const int koff = kc * BK;                      // halves
    const uint32_t sb = su + (uint32_t)(s * STG_H) * 2u;
    #pragma unroll
    for (int i = 0; i < 2; i++) {
        int idx = i * 256 + tid;                   // 0..511
        int r = idx >> 2, grp = idx & 3;           // row 0..127, 16B group 0..3
        uint32_t d = (uint32_t)(r * TSTR + grp * 8) * 2u;
        const __half* az = g_zh + (size_t)(row0 + r) * Dd + koff + grp * 8;
        const __half* al = g_zl + (size_t)(row0 + r) * Dd + koff + grp * 8;
        const __half* bc = g_ch + (size_t)(col0 + r) * Dd + koff + grp * 8;
        const __half* bl = g_cl + (size_t)(col0 + r) * Dd + koff + grp * 8;
        cp16(sb + d,                 az);
        cp16(sb + (uint32_t)T_H * 2u     + d, al);
        cp16(sb + (uint32_t)T_H * 4u     + d, bc);
        cp16(sb + (uint32_t)T_H * 6u     + d, bl);
    }
    asm volatile("cp.async.commit_group;" ::: "memory");
}

// ---------------------------------------------------------------------------
// fp16x3 GEMM: logits = 10*(z@C^T) - 5*csq, via zh.ch + zl.ch + zh.cl
// 1024 CTAs, 256 threads, 2-stage cp.async, warp tile 32x64
// ---------------------------------------------------------------------------
__global__ void __launch_bounds__(256, 2) gemm_kernel() {
    extern __shared__ __half sm[];
    const int tid  = threadIdx.x;
    const int w    = tid >> 5;
    const int lane = tid & 31;
    const int g    = lane >> 2;     // groupID
    const int tg   = lane & 3;      // threadID-in-group
    const int wm   = w >> 1;        // 0..3 (M)
    const int wn   = w & 1;         // 0..1 (N)
    const int mt   = blockIdx.x >> 3, nt = blockIdx.x & 7;
    const int row0 = mt * BM, col0 = nt * BN;
    const int mbase = wm * 32, nbase = wn * 64;

    const uint32_t su = smem_u32(sm);

    float acc[2][8][4];
    #pragma unroll
    for (int i = 0; i < 2; i++)
        #pragma unroll
        for (int j = 0; j < 8; j++)
            #pragma unroll
            for (int q = 0; q < 4; q++) acc[i][j][q] = 0.f;

    stage_chunk(su, 0, 0, row0, col0, tid);
    stage_chunk(su, 1, 1, row0, col0, tid);

    #pragma unroll 1
    for (int kc = 0; kc < NCH; kc++) {
        const int s = kc & 1;
        if (kc < NCH - 1) asm volatile("cp.async.wait_group 1;" ::: "memory");
        else              asm volatile("cp.async.wait_group 0;" ::: "memory");
        __syncthreads();

        const __half* Ah = sm + s * STG_H;
        const __half* Al = Ah + T_H;
        const __half* Bh = Ah + 2 * T_H;
        const __half* Bl = Ah + 3 * T_H;

        #pragma unroll
        for (int kq = 0; kq < 2; kq++) {
            const int kh = kq * 16;                 // k-half offset in halves
            uint32_t ah[2][4], al[2][4], bh[8][2], bl[8][2];
            #pragma unroll
            for (int i = 0; i < 2; i++) {
                const __half* p = Ah + (mbase + i * 16 + g) * TSTR + kh + 2 * tg;
                const __half* q = Al + (mbase + i * 16 + g) * TSTR + kh + 2 * tg;
                ah[i][0] = *reinterpret_cast<const uint32_t*>(p);
                ah[i][1] = *reinterpret_cast<const uint32_t*>(p + 8 * TSTR);
                ah[i][2] = *reinterpret_cast<const uint32_t*>(p + 8);
                ah[i][3] = *reinterpret_cast<const uint32_t*>(p + 8 * TSTR + 8);
                al[i][0] = *reinterpret_cast<const uint32_t*>(q);
                al[i][1] = *reinterpret_cast<const uint32_t*>(q + 8 * TSTR);
                al[i][2] = *reinterpret_cast<const uint32_t*>(q + 8);
                al[i][3] = *reinterpret_cast<const uint32_t*>(q + 8 * TSTR + 8);
            }
            #pragma unroll
            for (int j = 0; j < 8; j++) {
                const __half* p = Bh + (nbase + j * 8 + g) * TSTR + kh + 2 * tg;
                const __half* q = Bl + (nbase + j * 8 + g) * TSTR + kh + 2 * tg;
                bh[j][0] = *reinterpret_cast<const uint32_t*>(p);
                bh[j][1] = *reinterpret_cast<const uint32_t*>(p + 8);
                bl[j][0] = *reinterpret_cast<const uint32_t*>(q);
                bl[j][1] = *reinterpret_cast<const uint32_t*>(q + 8);
            }
            #pragma unroll
            for (int i = 0; i < 2; i++)
                #pragma unroll
                for (int j = 0; j < 8; j++) {
                    mma_f16(acc[i][j], ah[i], bh[j]);   // zh . ch
                    mma_f16(acc[i][j], al[i], bh[j]);   // zl . ch
                    mma_f16(acc[i][j], ah[i], bl[j]);   // zh . cl
                }
        }
        __syncthreads();
        if (kc + 2 < NCH) stage_chunk(su, s, kc + 2, row0, col0, tid);
    }

    // Epilogue: logits = 10*acc - 5*csq[col]
    #pragma unroll
    for (int i = 0; i < 2; i++) {
        const size_t r0 = (size_t)(row0 + mbase + i * 16 + g);
        #pragma unroll
        for (int j = 0; j < 8; j++) {
            const int col = col0 + nbase + j * 8 + 2 * tg;
            float2 cs = *reinterpret_cast<const float2*>(g_csq + col);
            float2 v0 = make_float2(fmaf(10.f, acc[i][j][0], -5.f * cs.x),
                                    fmaf(10.f, acc[i][j][1], -5.f * cs.y));
            float2 v1 = make_float2(fmaf(10.f, acc[i][j][2], -5.f * cs.x),
                                    fmaf(10.f, acc[i][j][3], -5.f * cs.y));
            *reinterpret_cast<float2*>(g_dot + r0 * Kk + col)       = v0;
            *reinterpret_cast<float2*>(g_dot + (r0 + 8) * Kk + col) = v1;
        }
    }
}

// ---------------------------------------------------------------------------
// Phase 2: single-pass softmax/argmax + gamma + recons + EMA scatters
// One warp per z-row; logits held in registers (32/lane)
// ---------------------------------------------------------------------------
__global__ void __launch_bounds__(256) softmax_kernel(const float* __restrict__ z,
                                                      const float* __restrict__ cent,
                                                      float* __restrict__ recons,
                                                      float* __restrict__ gamma) {
    const int w = threadIdx.x >> 5, lane = threadIdx.x & 31;
    const int row = blockIdx.x * 8 + w;
    const float* L = g_dot + (size_t)row * Kk;

    float4 lv[8];
    #pragma unroll
    for (int j = 0; j < 8; j++)
        lv[j] = *reinterpret_cast<const float4*>(L + (lane + 32 * j) * 4);

    // max + first-index argmax (ascending per-lane scan, min-index tiebreak)
    float m = -1e30f; int mi = 0;
    #pragma unroll
    for (int j = 0; j < 8; j++) {
        int b0 = (lane + 32 * j) * 4;
        if (lv[j].x > m) { m = lv[j].x; mi = b0;     }
        if (lv[j].y > m) { m = lv[j].y; mi = b0 + 1; }
        if (lv[j].z > m) { m = lv[j].z; mi = b0 + 2; }
        if (lv[j].w > m) { m = lv[j].w; mi = b0 + 3; }
    }
    #pragma unroll
    for (int o = 16; o > 0; o >>= 1) {
        float om = __shfl_xor_sync(0xffffffffu, m,  o);
        int   oi = __shfl_xor_sync(0xffffffffu, mi, o);
        if (om > m || (om == m && oi < mi)) { m = om; mi = oi; }
    }

    // exp + sum (in registers)
    float s = 0.f;
    #pragma unroll
    for (int j = 0; j < 8; j++) {
        lv[j].x = __expf(lv[j].x - m);
        lv[j].y = __expf(lv[j].y - m);
        lv[j].z = __expf(lv[j].z - m);
        lv[j].w = __expf(lv[j].w - m);
        s += lv[j].x + lv[j].y + lv[j].z + lv[j].w;
    }
    #pragma unroll
    for (int o = 16; o > 0; o >>= 1) s += __shfl_xor_sync(0xffffffffu, s, o);
    const float inv = 1.f / s;

    float* G = gamma + (size_t)row * Kk;
    #pragma unroll
    for (int j = 0; j < 8; j++) {
        float4 gv = make_float4(lv[j].x * inv, lv[j].y * inv, lv[j].z * inv, lv[j].w * inv);
        *reinterpret_cast<float4*>(G + (lane + 32 * j) * 4) = gv;
    }

    // recons = z + (c[k*] - z); EMA scatters
    const float4* crow = reinterpret_cast<const float4*>(cent   + (size_t)mi  * Dd);
    const float4* zrow = reinterpret_cast<const float4*>(z      + (size_t)row * Dd);
    float4*       rrow = reinterpret_cast<float4*>      (recons + (size_t)row * Dd);
    float* dwr = g_dw + (size_t)mi * Dd;
    #pragma unroll
    for (int j2 = 0; j2 < 2; j2++) {
        int d4 = lane + 32 * j2;
        float4 zv = zrow[d4];
        float4 cv = crow[d4];
        float4 rv;
        rv.x = zv.x + (cv.x - zv.x);
        rv.y = zv.y + (cv.y - zv.y);
        rv.z = zv.z + (cv.z - zv.z);
        rv.w = zv.w + (cv.w - zv.w);
        rrow[d4] = rv;
        atomicAdd(dwr + d4 * 4 + 0, zv.x);
        atomicAdd(dwr + d4 * 4 + 1, zv.y);
        atomicAdd(dwr + d4 * 4 + 2, zv.z);
        atomicAdd(dwr + d4 * 4 + 3, zv.w);
    }
    if (lane == 0) atomicAdd(&g_counts[mi], 1.f);
}

// ---------------------------------------------------------------------------
__global__ void norm_kernel(const float* __restrict__ ema_cs) {
    int k = threadIdx.x, lane = k & 31, wrp = k >> 5;
    float ncs = ema_cs[k] * 0.95f + 0.05f * g_counts[k];
    __shared__ float red[32];
    __shared__ float n_sh;
    float s = ncs;
    #pragma unroll
    for (int o = 16; o > 0; o >>= 1) s += __shfl_down_sync(0xffffffffu, s, o);
    if (lane == 0) red[wrp] = s;
    __syncthreads();
    if (k < 32) {
        float x = red[k];
        #pragma unroll
        for (int o = 16; o > 0; o >>= 1) x += __shfl_down_sync(0xffffffffu, x, o);
        if (k == 0) n_sh = x;
    }
    __syncthreads();
    float n = n_sh;
    g_ncs[k] = (ncs + 1e-5f) / (n + 0.01024f) * n;
}

__global__ void finalize_kernel(const float* __restrict__ ema_w, float* __restrict__ out) {
    int k = blockIdx.x, d = threadIdx.x;
    size_t i = (size_t)k * Dd + d;
    out[i] = (ema_w[i] * 0.95f + 0.05f * g_dw[i]) / g_ncs[k];
}

// ---------------------------------------------------------------------------
extern "C" void kernel_launch(void* const* d_in, const int* in_sizes, int n_in,
                              void* d_out, int out_size) {
    const float* z      = (const float*)d_in[0];
    const float* cent   = (const float*)d_in[1];
    const float* ema_w  = (const float*)d_in[2];
    const float* ema_cs = (const float*)d_in[3];

    float* out    = (float*)d_out;
    float* recons = out;
    float* gamma  = out + (size_t)Nz * Dd;
    float* newc   = out + (size_t)Nz * Dd + (size_t)Nz * Kk;

    cudaFuncSetAttribute(gemm_kernel, cudaFuncAttributeMaxDynamicSharedMemorySize, SMEM_BYTES);

    split_z_kernel<<<Nz * Dd / 4 / 256, 256>>>(z);
    split_c_kernel<<<Kk, 256>>>(cent);
    gemm_kernel<<<(Nz / BM) * (Kk / BN), 256, SMEM_BYTES>>>();
    softmax_kernel<<<Nz / 8, 256>>>(z, cent, recons, gamma);
    norm_kernel<<<1, Kk>>>(ema_cs);
    finalize_kernel<<<Kk, Dd>>>(ema_w, newc);
}

// round 5
// speedup vs baseline: 2.7495x; 1.0425x over previous
#include <cuda_runtime.h>
#include <cuda_fp16.h>
#include <cstdint>

// Problem sizes
#define Nz 16384
#define Dd 256
#define Kk 1024

// GEMM tiling
#define BM 128
#define BN 128
#define BK 32                    // k floats per chunk
#define NCH (Dd / BK)            // 8 chunks
#define TSTR 40                  // tile row stride in halves (conflict-free for ldmatrix)
#define T_H  (128 * TSTR)        // tile size in halves (5120)
#define STG_H (4 * T_H)          // stage: Azh, Azl, Bch, Bcl
#define SMEM_BYTES (2 * STG_H * 2)   // 2 stages = 81920 B

// ---------------- device scratch ----------------
__device__ __align__(16) __half g_zh[Nz * Dd];
__device__ __align__(16) __half g_zl[Nz * Dd];
__device__ __align__(16) __half g_ch[Kk * Dd];
__device__ __align__(16) __half g_cl[Kk * Dd];
__device__ __align__(16) float  g_csq[Kk];
__device__ __align__(16) float  g_dot[(size_t)Nz * Kk];   // stores LOGITS (10*dot-5*csq)
__device__ __align__(16) float  g_counts[Kk];
__device__ __align__(16) float  g_ncs[Kk];
__device__ __align__(16) float  g_dw[Kk * Dd];

// ---------------- helpers ----------------
__device__ __forceinline__ uint32_t smem_u32(const void* p) {
    uint32_t a;
    asm("{ .reg .u64 t; cvta.to.shared.u64 t, %1; cvt.u32.u64 %0, t; }" : "=r"(a) : "l"(p));
    return a;
}
__device__ __forceinline__ void cp16(uint32_t dst, const void* src) {
    asm volatile("cp.async.cg.shared.global [%0], [%1], 16;" :: "r"(dst), "l"(src));
}
__device__ __forceinline__ void ldsm4(uint32_t* r, uint32_t a) {
    asm volatile("ldmatrix.sync.aligned.m8n8.x4.shared.b16 {%0,%1,%2,%3}, [%4];"
                 : "=r"(r[0]), "=r"(r[1]), "=r"(r[2]), "=r"(r[3]) : "r"(a));
}
__device__ __forceinline__ void mma_f16(float* d, const uint32_t* a, const uint32_t* b) {
    asm volatile(
        "mma.sync.aligned.m16n8k16.row.col.f32.f16.f16.f32 "
        "{%0,%1,%2,%3}, {%4,%5,%6,%7}, {%8,%9}, {%0,%1,%2,%3};"
        : "+f"(d[0]), "+f"(d[1]), "+f"(d[2]), "+f"(d[3])
        : "r"(a[0]), "r"(a[1]), "r"(a[2]), "r"(a[3]), "r"(b[0]), "r"(b[1]));
}

// ---------------------------------------------------------------------------
// Split z into fp16 hi/lo (softmax is shift-invariant: -5*zsq constant dropped)
// ---------------------------------------------------------------------------
__global__ void split_z_kernel(const float* __restrict__ z) {
    int idx = blockIdx.x * 256 + threadIdx.x;          // over Nz*Dd/4
    float4 v = reinterpret_cast<const float4*>(z)[idx];
    __half hx = __float2half(v.x), hy = __float2half(v.y);
    __half hz = __float2half(v.z), hw = __float2half(v.w);
    __half lx = __float2half(v.x - __half2float(hx));
    __half ly = __float2half(v.y - __half2float(hy));
    __half lz = __float2half(v.z - __half2float(hz));
    __half lw = __float2half(v.w - __half2float(hw));
    half2 h01 = __halves2half2(hx, hy), h23 = __halves2half2(hz, hw);
    half2 l01 = __halves2half2(lx, ly), l23 = __halves2half2(lz, lw);
    reinterpret_cast<half2*>(g_zh)[idx * 2]     = h01;
    reinterpret_cast<half2*>(g_zh)[idx * 2 + 1] = h23;
    reinterpret_cast<half2*>(g_zl)[idx * 2]     = l01;
    reinterpret_cast<half2*>(g_zl)[idx * 2 + 1] = l23;
}

// ---------------------------------------------------------------------------
// Split centroids + csq + zero EMA scratch (graph replays need re-zero)
// ---------------------------------------------------------------------------
__global__ void split_c_kernel(const float* __restrict__ cent) {
    int k = blockIdx.x, t = threadIdx.x;
    int i = k * Dd + t;
    float v = cent[i];
    __half h = __float2half(v);
    __half l = __float2half(v - __half2float(h));
    g_ch[i] = h;
    g_cl[i] = l;
    g_dw[i] = 0.f;

    float s = v * v;
    #pragma unroll
    for (int o = 16; o > 0; o >>= 1) s += __shfl_down_sync(0xffffffffu, s, o);
    __shared__ float red[8];
    if ((t & 31) == 0) red[t >> 5] = s;
    __syncthreads();
    if (t == 0) {
        float x = 0.f;
        #pragma unroll
        for (int j = 0; j < 8; j++) x += red[j];
        g_csq[k]    = x;
        g_counts[k] = 0.f;
    }
}

// ---------------------------------------------------------------------------
// Stage one K-chunk: Azh, Azl (128x32h) + Bch, Bcl (128x32h) via cp.async
// ---------------------------------------------------------------------------
__device__ __forceinline__ void stage_chunk(uint32_t su, int s, int kc,
                                            int row0, int col0, int tid) {
    const int koff = kc * BK;                      // halves
    const uint32_t sb = su + (uint32_t)(s * STG_H) * 2u;
    #pragma unroll
    for (int i = 0; i < 2; i++) {
        int idx = i * 256 + tid;                   // 0..511
        int r = idx >> 2, grp = idx & 3;           // row 0..127, 16B group 0..3
        uint32_t d = (uint32_t)(r * TSTR + grp * 8) * 2u;
        const __half* az = g_zh + (size_t)(row0 + r) * Dd + koff + grp * 8;
        const __half* al = g_zl + (size_t)(row0 + r) * Dd + koff + grp * 8;
        const __half* bc = g_ch + (size_t)(col0 + r) * Dd + koff + grp * 8;
        const __half* bl = g_cl + (size_t)(col0 + r) * Dd + koff + grp * 8;
        cp16(sb + d,                      az);
        cp16(sb + (uint32_t)T_H * 2u + d, al);
        cp16(sb + (uint32_t)T_H * 4u + d, bc);
        cp16(sb + (uint32_t)T_H * 6u + d, bl);
    }
    asm volatile("cp.async.commit_group;" ::: "memory");
}

// ---------------------------------------------------------------------------
// fp16x3 GEMM: logits = 10*(z@C^T) - 5*csq, via zh.ch + zl.ch + zh.cl
// 1024 CTAs, 256 threads, 2-stage cp.async, warp tile 32x64, ldmatrix operands
// ---------------------------------------------------------------------------
__global__ void __launch_bounds__(256, 2) gemm_kernel() {
    extern __shared__ __half sm[];
    const int tid  = threadIdx.x;
    const int w    = tid >> 5;
    const int lane = tid & 31;
    const int wm   = w >> 1;        // 0..3 (M)
    const int wn   = w & 1;         // 0..1 (N)
    const int mt   = blockIdx.x >> 3, nt = blockIdx.x & 7;
    const int row0 = mt * BM, col0 = nt * BN;
    const int mbase = wm * 32, nbase = wn * 64;

    const uint32_t su = smem_u32(sm);

    // ldmatrix per-lane address offsets (bytes within a tile)
    const uint32_t aoff = (uint32_t)((mbase + (lane & 15)) * TSTR + (lane >> 4) * 8) * 2u;
    const int r8 = lane & 7, sel = lane >> 3;
    const uint32_t boff = (uint32_t)((nbase + (sel >> 1) * 8 + r8) * TSTR + (sel & 1) * 8) * 2u;

    float acc[2][8][4];
    #pragma unroll
    for (int i = 0; i < 2; i++)
        #pragma unroll
        for (int j = 0; j < 8; j++)
            #pragma unroll
            for (int q = 0; q < 4; q++) acc[i][j][q] = 0.f;

    stage_chunk(su, 0, 0, row0, col0, tid);
    stage_chunk(su, 1, 1, row0, col0, tid);

    #pragma unroll 1
    for (int kc = 0; kc < NCH; kc++) {
        const int s = kc & 1;
        if (kc < NCH - 1) asm volatile("cp.async.wait_group 1;" ::: "memory");
        else              asm volatile("cp.async.wait_group 0;" ::: "memory");
        __syncthreads();

        const uint32_t Ah = su + (uint32_t)(s * STG_H) * 2u;
        const uint32_t Al = Ah + (uint32_t)T_H * 2u;
        const uint32_t Bh = Ah + (uint32_t)T_H * 4u;
        const uint32_t Bl = Ah + (uint32_t)T_H * 6u;

        #pragma unroll
        for (int kq = 0; kq < 2; kq++) {
            const uint32_t kb = (uint32_t)kq * 32u;      // 16 halves = 32 bytes
            uint32_t ah[2][4], al[2][4], bh[8][2], bl[8][2];
            #pragma unroll
            for (int i = 0; i < 2; i++) {
                const uint32_t d = aoff + (uint32_t)(i * 16 * TSTR) * 2u + kb;
                ldsm4(ah[i], Ah + d);
                ldsm4(al[i], Al + d);
            }
            #pragma unroll
            for (int p = 0; p < 4; p++) {
                const uint32_t d = boff + (uint32_t)(p * 16 * TSTR) * 2u + kb;
                ldsm4(&bh[2 * p][0], Bh + d);   // fills bh[2p][0..1], bh[2p+1][0..1]
                ldsm4(&bl[2 * p][0], Bl + d);
            }
            #pragma unroll
            for (int i = 0; i < 2; i++)
                #pragma unroll
                for (int j = 0; j < 8; j++) {
                    mma_f16(acc[i][j], ah[i], bh[j]);   // zh . ch
                    mma_f16(acc[i][j], al[i], bh[j]);   // zl . ch
                    mma_f16(acc[i][j], ah[i], bl[j]);   // zh . cl
                }
        }
        __syncthreads();
        if (kc + 2 < NCH) stage_chunk(su, s, kc + 2, row0, col0, tid);
    }

    // Epilogue: logits = 10*acc - 5*csq[col]
    const int g  = lane >> 2;
    const int tg = lane & 3;
    #pragma unroll
    for (int i = 0; i < 2; i++) {
        const size_t r0 = (size_t)(row0 + mbase + i * 16 + g);
        #pragma unroll
        for (int j = 0; j < 8; j++) {
            const int col = col0 + nbase + j * 8 + 2 * tg;
            float2 cs = *reinterpret_cast<const float2*>(g_csq + col);
            float2 v0 = make_float2(fmaf(10.f, acc[i][j][0], -5.f * cs.x),
                                    fmaf(10.f, acc[i][j][1], -5.f * cs.y));
            float2 v1 = make_float2(fmaf(10.f, acc[i][j][2], -5.f * cs.x),
                                    fmaf(10.f, acc[i][j][3], -5.f * cs.y));
            *reinterpret_cast<float2*>(g_dot + r0 * Kk + col)       = v0;
            *reinterpret_cast<float2*>(g_dot + (r0 + 8) * Kk + col) = v1;
        }
    }
}

// ---------------------------------------------------------------------------
// Phase 2: single-pass softmax/argmax + gamma + recons + EMA scatters
// One warp per z-row; logits held in registers (32/lane)
// ---------------------------------------------------------------------------
__global__ void __launch_bounds__(256) softmax_kernel(const float* __restrict__ z,
                                                      const float* __restrict__ cent,
                                                      float* __restrict__ recons,
                                                      float* __restrict__ gamma) {
    const int w = threadIdx.x >> 5, lane = threadIdx.x & 31;
    const int row = blockIdx.x * 8 + w;
    const float* L = g_dot + (size_t)row * Kk;

    float4 lv[8];
    #pragma unroll
    for (int j = 0; j < 8; j++)
        lv[j] = __ldcs(reinterpret_cast<const float4*>(L + (lane + 32 * j) * 4));

    // max + first-index argmax (ascending per-lane scan, min-index tiebreak)
    float m = -1e30f; int mi = 0;
    #pragma unroll
    for (int j = 0; j < 8; j++) {
        int b0 = (lane + 32 * j) * 4;
        if (lv[j].x > m) { m = lv[j].x; mi = b0;     }
        if (lv[j].y > m) { m = lv[j].y; mi = b0 + 1; }
        if (lv[j].z > m) { m = lv[j].z; mi = b0 + 2; }
        if (lv[j].w > m) { m = lv[j].w; mi = b0 + 3; }
    }
    #pragma unroll
    for (int o = 16; o > 0; o >>= 1) {
        float om = __shfl_xor_sync(0xffffffffu, m,  o);
        int   oi = __shfl_xor_sync(0xffffffffu, mi, o);
        if (om > m || (om == m && oi < mi)) { m = om; mi = oi; }
    }

    // exp + sum (in registers)
    float s = 0.f;
    #pragma unroll
    for (int j = 0; j < 8; j++) {
        lv[j].x = __expf(lv[j].x - m);
        lv[j].y = __expf(lv[j].y - m);
        lv[j].z = __expf(lv[j].z - m);
        lv[j].w = __expf(lv[j].w - m);
        s += lv[j].x + lv[j].y + lv[j].z + lv[j].w;
    }
    #pragma unroll
    for (int o = 16; o > 0; o >>= 1) s += __shfl_xor_sync(0xffffffffu, s, o);
    const float inv = 1.f / s;

    float* G = gamma + (size_t)row * Kk;
    #pragma unroll
    for (int j = 0; j < 8; j++) {
        float4 gv = make_float4(lv[j].x * inv, lv[j].y * inv, lv[j].z * inv, lv[j].w * inv);
        __stcs(reinterpret_cast<float4*>(G + (lane + 32 * j) * 4), gv);
    }

    // recons = z + (c[k*] - z); EMA scatters
    const float4* crow = reinterpret_cast<const float4*>(cent   + (size_t)mi  * Dd);
    const float4* zrow = reinterpret_cast<const float4*>(z      + (size_t)row * Dd);
    float4*       rrow = reinterpret_cast<float4*>      (recons + (size_t)row * Dd);
    float* dwr = g_dw + (size_t)mi * Dd;
    #pragma unroll
    for (int j2 = 0; j2 < 2; j2++) {
        int d4 = lane + 32 * j2;
        float4 zv = zrow[d4];
        float4 cv = crow[d4];
        float4 rv;
        rv.x = zv.x + (cv.x - zv.x);
        rv.y = zv.y + (cv.y - zv.y);
        rv.z = zv.z + (cv.z - zv.z);
        rv.w = zv.w + (cv.w - zv.w);
        __stcs(rrow + d4, rv);
        atomicAdd(dwr + d4 * 4 + 0, zv.x);
        atomicAdd(dwr + d4 * 4 + 1, zv.y);
        atomicAdd(dwr + d4 * 4 + 2, zv.z);
        atomicAdd(dwr + d4 * 4 + 3, zv.w);
    }
    if (lane == 0) atomicAdd(&g_counts[mi], 1.f);
}

// ---------------------------------------------------------------------------
__global__ void norm_kernel(const float* __restrict__ ema_cs) {
    int k = threadIdx.x, lane = k & 31, wrp = k >> 5;
    float ncs = ema_cs[k] * 0.95f + 0.05f * g_counts[k];
    __shared__ float red[32];
    __shared__ float n_sh;
    float s = ncs;
    #pragma unroll
    for (int o = 16; o > 0; o >>= 1) s += __shfl_down_sync(0xffffffffu, s, o);
    if (lane == 0) red[wrp] = s;
    __syncthreads();
    if (k < 32) {
        float x = red[k];
        #pragma unroll
        for (int o = 16; o > 0; o >>= 1) x += __shfl_down_sync(0xffffffffu, x, o);
        if (k == 0) n_sh = x;
    }
    __syncthreads();
    float n = n_sh;
    g_ncs[k] = (ncs + 1e-5f) / (n + 0.01024f) * n;
}

__global__ void finalize_kernel(const float* __restrict__ ema_w, float* __restrict__ out) {
    int k = blockIdx.x, d = threadIdx.x;
    size_t i = (size_t)k * Dd + d;
    out[i] = (ema_w[i] * 0.95f + 0.05f * g_dw[i]) / g_ncs[k];
}

// ---------------------------------------------------------------------------
extern "C" void kernel_launch(void* const* d_in, const int* in_sizes, int n_in,
                              void* d_out, int out_size) {
    const float* z      = (const float*)d_in[0];
    const float* cent   = (const float*)d_in[1];
    const float* ema_w  = (const float*)d_in[2];
    const float* ema_cs = (const float*)d_in[3];

    float* out    = (float*)d_out;
    float* recons = out;
    float* gamma  = out + (size_t)Nz * Dd;
    float* newc   = out + (size_t)Nz * Dd + (size_t)Nz * Kk;

    cudaFuncSetAttribute(gemm_kernel, cudaFuncAttributeMaxDynamicSharedMemorySize, SMEM_BYTES);

    split_z_kernel<<<Nz * Dd / 4 / 256, 256>>>(z);
    split_c_kernel<<<Kk, 256>>>(cent);
    gemm_kernel<<<(Nz / BM) * (Kk / BN), 256, SMEM_BYTES>>>();
    softmax_kernel<<<Nz / 8, 256>>>(z, cent, recons, gamma);
    norm_kernel<<<1, Kk>>>(ema_cs);
    finalize_kernel<<<Kk, Dd>>>(ema_w, newc);
}